// round 15
// baseline (speedup 1.0000x reference)
#include <cuda_runtime.h>
#include <cuda_bf16.h>

#define NN 100000
#define EE 800000
#define DD 64
#define HH 4

typedef unsigned long long ull;

// Scratch (device globals; no allocation allowed)
__device__ float g_Q[NN * DD];
__device__ float g_K[NN * DD];
__device__ float g_V[NN * DD];
__device__ int   g_cnt[NN];
__device__ int   g_off[NN + 1];
__device__ int   g_cur[NN];
__device__ int   g_bsum[128];
__device__ int   g_scol[EE];

// ---------------------------------------------------------------------------
// Packed f32x2 helpers (sm_103a): ptxas never auto-fuses these.
// ---------------------------------------------------------------------------
__device__ __forceinline__ ull ffma2(ull a, ull b, ull c)
{
    ull d;
    asm("fma.rn.f32x2 %0, %1, %2, %3;" : "=l"(d) : "l"(a), "l"(b), "l"(c));
    return d;
}

__device__ __forceinline__ ull dup2(float w)
{
    ull u;
    asm("mov.b64 %0, {%1, %1};" : "=l"(u) : "f"(w));
    return u;
}

// ---------------------------------------------------------------------------
// 1) Node projections: grid (782, 3), blockIdx.y = matrix m.
//    Block = 256 threads computes [128 nodes] x [64 outputs] for matrix m.
//    Thread tile: 4 nodes x 8 outputs (4 d-pairs) -> 16 ull accumulators.
//    d-PAIR packing: acc = {C[n][d], C[n][d+1]}; W read straight from gmem
//    as packed ulls (16 KB working set, L1-resident) -> NO weight dups, and
//    the epilogue stores accs bitwise (ulonglong2 == float4).
//    W row stride = 64 floats = SIXTEEN ulonglong2s (R12 bug was k*8).
//    Per k: 16 FFMA2 + 4 LDS.32 + 2 LDG.128 + 4 dup = 26 instrs.
// ---------------------------------------------------------------------------
#define PB_NODES 128

__global__ __launch_bounds__(256) void proj_kernel(
    const float* __restrict__ X,
    const float* __restrict__ Wq,
    const float* __restrict__ Wk,
    const float* __restrict__ Wv)
{
    __shared__ float xs[PB_NODES][DD + 1];   // 33,280 B

    int tid   = threadIdx.x;
    int nbase = blockIdx.x * PB_NODES;
    int m     = blockIdx.y;

    // Stage X tile (coalesced float4 reads; zero-pad OOB nodes).
    for (int idx = tid; idx < PB_NODES * (DD / 4); idx += 256) {
        int nl = idx >> 4;
        int dq = idx & 15;
        int n  = nbase + nl;
        float4 v = (n < NN) ? ((const float4*)(X + (size_t)n * DD))[dq]
                            : make_float4(0.f, 0.f, 0.f, 0.f);
        xs[nl][dq * 4 + 0] = v.x;
        xs[nl][dq * 4 + 1] = v.y;
        xs[nl][dq * 4 + 2] = v.z;
        xs[nl][dq * 4 + 3] = v.w;
    }
    __syncthreads();

    int dg = tid & 7;          // 8 d-groups x 8 outputs
    int ng = tid >> 3;         // 32 node-groups x 4 nodes
    int d0 = dg * 8;
    int n0 = ng * 4;

    const float* Wm = (m == 0) ? Wq : (m == 1) ? Wk : Wv;
    const ulonglong2* wp = (const ulonglong2*)(Wm + d0);
    // W row k starts at k*DD floats = k*16 ulonglong2s from wp.

    ull acc[4][4];
#pragma unroll
    for (int p = 0; p < 4; p++)
#pragma unroll
        for (int dp = 0; dp < 4; dp++) acc[p][dp] = 0ull;

#pragma unroll 8
    for (int k = 0; k < DD; k++) {
        // weights: 2 LDG.128 -> 4 packed d-pairs (L1 hits)
        ulonglong2 wa = wp[k * 16];        // floats [d0,   d0+4)
        ulonglong2 wb = wp[k * 16 + 1];    // floats [d0+4, d0+8)
        ull w0 = wa.x, w1 = wa.y, w2 = wb.x, w3 = wb.y;

        // x: 4 scalar LDS (conflict-free) + dup into both packed halves
        ull x0 = dup2(xs[n0 + 0][k]);
        ull x1 = dup2(xs[n0 + 1][k]);
        ull x2 = dup2(xs[n0 + 2][k]);
        ull x3 = dup2(xs[n0 + 3][k]);

        acc[0][0] = ffma2(x0, w0, acc[0][0]);
        acc[0][1] = ffma2(x0, w1, acc[0][1]);
        acc[0][2] = ffma2(x0, w2, acc[0][2]);
        acc[0][3] = ffma2(x0, w3, acc[0][3]);
        acc[1][0] = ffma2(x1, w0, acc[1][0]);
        acc[1][1] = ffma2(x1, w1, acc[1][1]);
        acc[1][2] = ffma2(x1, w2, acc[1][2]);
        acc[1][3] = ffma2(x1, w3, acc[1][3]);
        acc[2][0] = ffma2(x2, w0, acc[2][0]);
        acc[2][1] = ffma2(x2, w1, acc[2][1]);
        acc[2][2] = ffma2(x2, w2, acc[2][2]);
        acc[2][3] = ffma2(x2, w3, acc[2][3]);
        acc[3][0] = ffma2(x3, w0, acc[3][0]);
        acc[3][1] = ffma2(x3, w1, acc[3][1]);
        acc[3][2] = ffma2(x3, w2, acc[3][2]);
        acc[3][3] = ffma2(x3, w3, acc[3][3]);
    }

    float* base = (m == 0) ? g_Q : (m == 1) ? g_K : g_V;
#pragma unroll
    for (int p = 0; p < 4; p++) {
        int n = nbase + n0 + p;
        if (n < NN) {
            ulonglong2* o = (ulonglong2*)(base + (size_t)n * DD + d0);
            ulonglong2 v0; v0.x = acc[p][0]; v0.y = acc[p][1];
            ulonglong2 v1; v1.x = acc[p][2]; v1.y = acc[p][3];
            o[0] = v0;   // bitwise {C[d0..d0+4)}
            o[1] = v1;   // bitwise {C[d0+4..d0+8)}
        }
    }
}

// ---------------------------------------------------------------------------
// 2) CSR build. zero_cnt split in 3 parts (keeps ncu's fixed capture slot —
//    launch #4 — on proj_kernel).
// ---------------------------------------------------------------------------
__global__ void zero_cnt_part(int base, int n)
{
    int i = base + blockIdx.x * blockDim.x + threadIdx.x;
    if (i < base + n && i < NN) g_cnt[i] = 0;
}

__global__ void hist_kernel(const int* __restrict__ rows)
{
    int e4 = blockIdx.x * blockDim.x + threadIdx.x;
    if (e4 < EE / 4) {
        int4 r = ((const int4*)rows)[e4];
        atomicAdd(&g_cnt[r.x], 1);
        atomicAdd(&g_cnt[r.y], 1);
        atomicAdd(&g_cnt[r.z], 1);
        atomicAdd(&g_cnt[r.w], 1);
    }
}

__global__ __launch_bounds__(1024) void scan_block_kernel()
{
    __shared__ int wsum[32];
    int i    = blockIdx.x * 1024 + threadIdx.x;
    int lane = threadIdx.x & 31;
    int w    = threadIdx.x >> 5;
    int v    = (i < NN) ? g_cnt[i] : 0;

    int s = v;
#pragma unroll
    for (int o = 1; o < 32; o <<= 1) {
        int t = __shfl_up_sync(0xffffffffu, s, o);
        if (lane >= o) s += t;
    }
    if (lane == 31) wsum[w] = s;
    __syncthreads();

    if (w == 0) {
        int ws = wsum[lane];
        int t  = ws;
#pragma unroll
        for (int o = 1; o < 32; o <<= 1) {
            int u = __shfl_up_sync(0xffffffffu, t, o);
            if (lane >= o) t += u;
        }
        wsum[lane] = t - ws;
    }
    __syncthreads();

    int incl = s + wsum[w];
    if (i < NN) g_off[i] = incl - v;
    if (threadIdx.x == 1023) g_bsum[blockIdx.x] = incl;
}

__global__ void scan_sums_kernel(int nb)
{
    if (threadIdx.x == 0 && blockIdx.x == 0) {
        int acc = 0;
        for (int b = 0; b < nb; b++) { int t = g_bsum[b]; g_bsum[b] = acc; acc += t; }
    }
}

__global__ void add_off_kernel()
{
    int i = blockIdx.x * blockDim.x + threadIdx.x;
    if (i < NN) {
        int o = g_off[i] + g_bsum[i >> 10];
        g_off[i] = o;
        g_cur[i] = o;
    }
    if (i == 0) g_off[NN] = EE;
}

__global__ void scatter_kernel(const int* __restrict__ rows,
                               const int* __restrict__ cols)
{
    int e4 = blockIdx.x * blockDim.x + threadIdx.x;
    if (e4 < EE / 4) {
        int4 r = ((const int4*)rows)[e4];
        int4 c = ((const int4*)cols)[e4];
        int p0 = atomicAdd(&g_cur[r.x], 1);
        int p1 = atomicAdd(&g_cur[r.y], 1);
        int p2 = atomicAdd(&g_cur[r.z], 1);
        int p3 = atomicAdd(&g_cur[r.w], 1);
        g_scol[p0] = c.x;
        g_scol[p1] = c.y;
        g_scol[p2] = c.z;
        g_scol[p3] = c.w;
    }
}

// ---------------------------------------------------------------------------
// 3) Fused attention aggregate (known-good R4 layout: warp per node,
//    float2/lane), unrolled x4, scol batch loads rotated one iteration ahead.
// ---------------------------------------------------------------------------
__global__ __launch_bounds__(256) void aggregate_kernel(float* __restrict__ out)
{
    int warp = (blockIdx.x * blockDim.x + threadIdx.x) >> 5;
    int lane = threadIdx.x & 31;
    if (warp >= NN) return;

    int start = g_off[warp];
    int end   = g_off[warp + 1];

    float2 q   = *(const float2*)(g_Q + (size_t)warp * DD + lane * 2);
    float2 acc = make_float2(0.f, 0.f);
    float  na  = 0.f;

    int j = start;
    int c0 = 0, c1 = 0, c2 = 0, c3 = 0;
    if (j + 4 <= end) {
        c0 = __ldg(&g_scol[j + 0]);
        c1 = __ldg(&g_scol[j + 1]);
        c2 = __ldg(&g_scol[j + 2]);
        c3 = __ldg(&g_scol[j + 3]);
    }

    while (j + 4 <= end) {
        int u0 = c0, u1 = c1, u2 = c2, u3 = c3;
        int jn = j + 4;
        if (jn + 4 <= end) {
            c0 = __ldg(&g_scol[jn + 0]);
            c1 = __ldg(&g_scol[jn + 1]);
            c2 = __ldg(&g_scol[jn + 2]);
            c3 = __ldg(&g_scol[jn + 3]);
        }

        float2 k0 = *(const float2*)(g_K + (size_t)u0 * DD + lane * 2);
        float2 k1 = *(const float2*)(g_K + (size_t)u1 * DD + lane * 2);
        float2 k2 = *(const float2*)(g_K + (size_t)u2 * DD + lane * 2);
        float2 k3 = *(const float2*)(g_K + (size_t)u3 * DD + lane * 2);
        float2 v0 = *(const float2*)(g_V + (size_t)u0 * DD + lane * 2);
        float2 v1 = *(const float2*)(g_V + (size_t)u1 * DD + lane * 2);
        float2 v2 = *(const float2*)(g_V + (size_t)u2 * DD + lane * 2);
        float2 v3 = *(const float2*)(g_V + (size_t)u3 * DD + lane * 2);

        float p0 = q.x * k0.x + q.y * k0.y;
        float p1 = q.x * k1.x + q.y * k1.y;
        float p2 = q.x * k2.x + q.y * k2.y;
        float p3 = q.x * k3.x + q.y * k3.y;

        p0 += __shfl_xor_sync(0xffffffffu, p0, 1);
        p1 += __shfl_xor_sync(0xffffffffu, p1, 1);
        p2 += __shfl_xor_sync(0xffffffffu, p2, 1);
        p3 += __shfl_xor_sync(0xffffffffu, p3, 1);
        p0 += __shfl_xor_sync(0xffffffffu, p0, 2);
        p1 += __shfl_xor_sync(0xffffffffu, p1, 2);
        p2 += __shfl_xor_sync(0xffffffffu, p2, 2);
        p3 += __shfl_xor_sync(0xffffffffu, p3, 2);
        p0 += __shfl_xor_sync(0xffffffffu, p0, 4);
        p1 += __shfl_xor_sync(0xffffffffu, p1, 4);
        p2 += __shfl_xor_sync(0xffffffffu, p2, 4);
        p3 += __shfl_xor_sync(0xffffffffu, p3, 4);

        float e0 = __expf(fminf(10.f, fmaxf(-10.f, p0)));
        float e1 = __expf(fminf(10.f, fmaxf(-10.f, p1)));
        float e2 = __expf(fminf(10.f, fmaxf(-10.f, p2)));
        float e3 = __expf(fminf(10.f, fmaxf(-10.f, p3)));

        na += (e0 + e1) + (e2 + e3);
        acc.x += e0 * v0.x + e1 * v1.x + e2 * v2.x + e3 * v3.x;
        acc.y += e0 * v0.y + e1 * v1.y + e2 * v2.y + e3 * v3.y;

        j = jn;
    }

    for (; j < end; j++) {
        int c = __ldg(&g_scol[j]);
        float2 kv = *(const float2*)(g_K + (size_t)c * DD + lane * 2);
        float2 vv = *(const float2*)(g_V + (size_t)c * DD + lane * 2);
        float p = q.x * kv.x + q.y * kv.y;
        p += __shfl_xor_sync(0xffffffffu, p, 1);
        p += __shfl_xor_sync(0xffffffffu, p, 2);
        p += __shfl_xor_sync(0xffffffffu, p, 4);
        float ea = __expf(fminf(10.f, fmaxf(-10.f, p)));
        na += ea;
        acc.x += ea * vv.x;
        acc.y += ea * vv.y;
    }

    float inv = 1.f / (na + 1e-8f);
    *(float2*)(out + (size_t)warp * DD + lane * 2) =
        make_float2(acc.x * inv, acc.y * inv);
}

// ---------------------------------------------------------------------------
extern "C" void kernel_launch(void* const* d_in, const int* in_sizes, int n_in,
                              void* d_out, int out_size)
{
    const float* X  = (const float*)d_in[0];
    const float* Wq = (const float*)d_in[1];
    const float* Wk = (const float*)d_in[2];
    const float* Wv = (const float*)d_in[3];
    const int*   ei = (const int*)d_in[4];
    const int* rows = ei;
    const int* cols = ei + EE;
    float* out = (float*)d_out;

    (void)in_sizes; (void)n_in; (void)out_size;

    // zero counts in 3 parts (launches 1-3; proj stays at ncu capture slot #4)
    int third = (NN + 2) / 3;
    zero_cnt_part<<<(third + 255) / 256, 256>>>(0, third);
    zero_cnt_part<<<(third + 255) / 256, 256>>>(third, third);
    zero_cnt_part<<<(third + 255) / 256, 256>>>(2 * third, NN - 2 * third);

    // 1) node projections (tiled GEMM, grid.y = matrix; launch #4 — profiled)
    dim3 pgrid((NN + PB_NODES - 1) / PB_NODES, 3);
    proj_kernel<<<pgrid, 256>>>(X, Wq, Wk, Wv);

    // 2) CSR build by destination row
    hist_kernel<<<(EE / 4 + 255) / 256, 256>>>(rows);
    int nb = (NN + 1023) / 1024;
    scan_block_kernel<<<nb, 1024>>>();
    scan_sums_kernel<<<1, 32>>>(nb);
    add_off_kernel<<<(NN + 255) / 256, 256>>>();
    scatter_kernel<<<(EE / 4 + 255) / 256, 256>>>(rows, cols);

    // 3) fused gather + softmax + aggregate (one warp per node)
    aggregate_kernel<<<(NN * 32 + 255) / 256, 256>>>(out);
}

// round 16
// speedup vs baseline: 1.1452x; 1.1452x over previous
#include <cuda_runtime.h>
#include <cuda_bf16.h>

#define NN 100000
#define EE 800000
#define DD 64
#define HH 4

typedef unsigned long long ull;

// Scratch (device globals; no allocation allowed)
__device__ float g_Q[NN * DD];
__device__ float g_K[NN * DD];
__device__ float g_V[NN * DD];
__device__ int   g_cnt[NN];
__device__ int   g_off[NN + 1];
__device__ int   g_cur[NN];
__device__ int   g_bsum[128];
__device__ int   g_scol[EE];

// ---------------------------------------------------------------------------
// Packed f32x2 helpers (sm_103a): ptxas never auto-fuses these.
// ---------------------------------------------------------------------------
__device__ __forceinline__ ull ffma2(ull a, ull b, ull c)
{
    ull d;
    asm("fma.rn.f32x2 %0, %1, %2, %3;" : "=l"(d) : "l"(a), "l"(b), "l"(c));
    return d;
}

__device__ __forceinline__ ull dup2(float w)
{
    ull u;
    asm("mov.b64 %0, {%1, %1};" : "=l"(u) : "f"(w));
    return u;
}

// ---------------------------------------------------------------------------
// 1) Node projections: grid (782, 3), blockIdx.y = matrix m.
//    Block = 256 threads computes [128 nodes] x [64 outputs] for matrix m.
//    Thread tile: 4 nodes x 8 outputs as TWO float4 chunks at d_lo = dg*4 and
//    d_hi = 32 + dg*4  ->  the warp's 8 dg-lanes cover each 256B weight row as
//    two CONTIGUOUS 128B halves (1 wavefront per LDG.128, was 2).
//    k processed in chunks of 4: one LDS.128 per node per chunk (xs row
//    stride 68 floats keeps 16B alignment) replaces 16 LDS.32.
//    Per 4k per thread: 8 LDG.128 + 4 LDS.128 + 16 dup + 64 FFMA2 -> FMA-bound.
// ---------------------------------------------------------------------------
#define PB_NODES  128
#define XS_STRIDE 68

__global__ __launch_bounds__(256) void proj_kernel(
    const float* __restrict__ X,
    const float* __restrict__ Wq,
    const float* __restrict__ Wk,
    const float* __restrict__ Wv)
{
    __shared__ float xs[PB_NODES][XS_STRIDE];   // 34,816 B

    int tid   = threadIdx.x;
    int nbase = blockIdx.x * PB_NODES;
    int m     = blockIdx.y;

    // Stage X tile (coalesced float4 reads; zero-pad OOB nodes).
    for (int idx = tid; idx < PB_NODES * (DD / 4); idx += 256) {
        int nl = idx >> 4;
        int dq = idx & 15;
        int n  = nbase + nl;
        float4 v = (n < NN) ? ((const float4*)(X + (size_t)n * DD))[dq]
                            : make_float4(0.f, 0.f, 0.f, 0.f);
        xs[nl][dq * 4 + 0] = v.x;
        xs[nl][dq * 4 + 1] = v.y;
        xs[nl][dq * 4 + 2] = v.z;
        xs[nl][dq * 4 + 3] = v.w;
    }
    __syncthreads();

    int dg   = tid & 7;            // 8 d-groups
    int ng   = tid >> 3;           // 32 node-groups x 4 nodes
    int d_lo = dg * 4;             // first float4 chunk  (row bytes [dg*16, +16))
    int d_hi = 32 + dg * 4;        // second float4 chunk (row bytes [128+dg*16, +16))
    int n0   = ng * 4;

    const float* Wm = (m == 0) ? Wq : (m == 1) ? Wk : Wv;
    const ulonglong2* wlo = (const ulonglong2*)(Wm + d_lo);   // row k: + k*16
    const ulonglong2* whi = (const ulonglong2*)(Wm + d_hi);

    // acc[p][0..1] = d-pairs of d_lo chunk, acc[p][2..3] = d-pairs of d_hi.
    ull acc[4][4];
#pragma unroll
    for (int p = 0; p < 4; p++)
#pragma unroll
        for (int dp = 0; dp < 4; dp++) acc[p][dp] = 0ull;

#pragma unroll 4
    for (int kc = 0; kc < DD; kc += 4) {
        float4 xv0 = *(const float4*)&xs[n0 + 0][kc];
        float4 xv1 = *(const float4*)&xs[n0 + 1][kc];
        float4 xv2 = *(const float4*)&xs[n0 + 2][kc];
        float4 xv3 = *(const float4*)&xs[n0 + 3][kc];
        const float* xf0 = (const float*)&xv0;
        const float* xf1 = (const float*)&xv1;
        const float* xf2 = (const float*)&xv2;
        const float* xf3 = (const float*)&xv3;

#pragma unroll
        for (int kk = 0; kk < 4; kk++) {
            int k = kc + kk;
            ulonglong2 wa = wlo[k * 16];   // 1 coalesced wavefront across warp
            ulonglong2 wb = whi[k * 16];   // 1 coalesced wavefront across warp
            ull w0 = wa.x, w1 = wa.y, w2 = wb.x, w3 = wb.y;

            ull x0 = dup2(xf0[kk]);
            ull x1 = dup2(xf1[kk]);
            ull x2 = dup2(xf2[kk]);
            ull x3 = dup2(xf3[kk]);

            acc[0][0] = ffma2(x0, w0, acc[0][0]);
            acc[0][1] = ffma2(x0, w1, acc[0][1]);
            acc[0][2] = ffma2(x0, w2, acc[0][2]);
            acc[0][3] = ffma2(x0, w3, acc[0][3]);
            acc[1][0] = ffma2(x1, w0, acc[1][0]);
            acc[1][1] = ffma2(x1, w1, acc[1][1]);
            acc[1][2] = ffma2(x1, w2, acc[1][2]);
            acc[1][3] = ffma2(x1, w3, acc[1][3]);
            acc[2][0] = ffma2(x2, w0, acc[2][0]);
            acc[2][1] = ffma2(x2, w1, acc[2][1]);
            acc[2][2] = ffma2(x2, w2, acc[2][2]);
            acc[2][3] = ffma2(x2, w3, acc[2][3]);
            acc[3][0] = ffma2(x3, w0, acc[3][0]);
            acc[3][1] = ffma2(x3, w1, acc[3][1]);
            acc[3][2] = ffma2(x3, w2, acc[3][2]);
            acc[3][3] = ffma2(x3, w3, acc[3][3]);
        }
    }

    float* base = (m == 0) ? g_Q : (m == 1) ? g_K : g_V;
#pragma unroll
    for (int p = 0; p < 4; p++) {
        int n = nbase + n0 + p;
        if (n < NN) {
            ulonglong2 vlo; vlo.x = acc[p][0]; vlo.y = acc[p][1];
            ulonglong2 vhi; vhi.x = acc[p][2]; vhi.y = acc[p][3];
            *(ulonglong2*)(base + (size_t)n * DD + d_lo) = vlo;  // bitwise float4
            *(ulonglong2*)(base + (size_t)n * DD + d_hi) = vhi;  // bitwise float4
        }
    }
}

// ---------------------------------------------------------------------------
// 2) CSR build. zero_cnt split in 3 parts (keeps ncu's fixed capture slot —
//    launch #4 — on proj_kernel).
// ---------------------------------------------------------------------------
__global__ void zero_cnt_part(int base, int n)
{
    int i = base + blockIdx.x * blockDim.x + threadIdx.x;
    if (i < base + n && i < NN) g_cnt[i] = 0;
}

__global__ void hist_kernel(const int* __restrict__ rows)
{
    int e4 = blockIdx.x * blockDim.x + threadIdx.x;
    if (e4 < EE / 4) {
        int4 r = ((const int4*)rows)[e4];
        atomicAdd(&g_cnt[r.x], 1);
        atomicAdd(&g_cnt[r.y], 1);
        atomicAdd(&g_cnt[r.z], 1);
        atomicAdd(&g_cnt[r.w], 1);
    }
}

__global__ __launch_bounds__(1024) void scan_block_kernel()
{
    __shared__ int wsum[32];
    int i    = blockIdx.x * 1024 + threadIdx.x;
    int lane = threadIdx.x & 31;
    int w    = threadIdx.x >> 5;
    int v    = (i < NN) ? g_cnt[i] : 0;

    int s = v;
#pragma unroll
    for (int o = 1; o < 32; o <<= 1) {
        int t = __shfl_up_sync(0xffffffffu, s, o);
        if (lane >= o) s += t;
    }
    if (lane == 31) wsum[w] = s;
    __syncthreads();

    if (w == 0) {
        int ws = wsum[lane];
        int t  = ws;
#pragma unroll
        for (int o = 1; o < 32; o <<= 1) {
            int u = __shfl_up_sync(0xffffffffu, t, o);
            if (lane >= o) t += u;
        }
        wsum[lane] = t - ws;
    }
    __syncthreads();

    int incl = s + wsum[w];
    if (i < NN) g_off[i] = incl - v;
    if (threadIdx.x == 1023) g_bsum[blockIdx.x] = incl;
}

__global__ void scan_sums_kernel(int nb)
{
    if (threadIdx.x == 0 && blockIdx.x == 0) {
        int acc = 0;
        for (int b = 0; b < nb; b++) { int t = g_bsum[b]; g_bsum[b] = acc; acc += t; }
    }
}

__global__ void add_off_kernel()
{
    int i = blockIdx.x * blockDim.x + threadIdx.x;
    if (i < NN) {
        int o = g_off[i] + g_bsum[i >> 10];
        g_off[i] = o;
        g_cur[i] = o;
    }
    if (i == 0) g_off[NN] = EE;
}

__global__ void scatter_kernel(const int* __restrict__ rows,
                               const int* __restrict__ cols)
{
    int e4 = blockIdx.x * blockDim.x + threadIdx.x;
    if (e4 < EE / 4) {
        int4 r = ((const int4*)rows)[e4];
        int4 c = ((const int4*)cols)[e4];
        int p0 = atomicAdd(&g_cur[r.x], 1);
        int p1 = atomicAdd(&g_cur[r.y], 1);
        int p2 = atomicAdd(&g_cur[r.z], 1);
        int p3 = atomicAdd(&g_cur[r.w], 1);
        g_scol[p0] = c.x;
        g_scol[p1] = c.y;
        g_scol[p2] = c.z;
        g_scol[p3] = c.w;
    }
}

// ---------------------------------------------------------------------------
// 3) Fused attention aggregate (known-good R4 layout: warp per node,
//    float2/lane), unrolled x4, scol batch loads rotated one iteration ahead.
// ---------------------------------------------------------------------------
__global__ __launch_bounds__(256) void aggregate_kernel(float* __restrict__ out)
{
    int warp = (blockIdx.x * blockDim.x + threadIdx.x) >> 5;
    int lane = threadIdx.x & 31;
    if (warp >= NN) return;

    int start = g_off[warp];
    int end   = g_off[warp + 1];

    float2 q   = *(const float2*)(g_Q + (size_t)warp * DD + lane * 2);
    float2 acc = make_float2(0.f, 0.f);
    float  na  = 0.f;

    int j = start;
    int c0 = 0, c1 = 0, c2 = 0, c3 = 0;
    if (j + 4 <= end) {
        c0 = __ldg(&g_scol[j + 0]);
        c1 = __ldg(&g_scol[j + 1]);
        c2 = __ldg(&g_scol[j + 2]);
        c3 = __ldg(&g_scol[j + 3]);
    }

    while (j + 4 <= end) {
        int u0 = c0, u1 = c1, u2 = c2, u3 = c3;
        int jn = j + 4;
        if (jn + 4 <= end) {
            c0 = __ldg(&g_scol[jn + 0]);
            c1 = __ldg(&g_scol[jn + 1]);
            c2 = __ldg(&g_scol[jn + 2]);
            c3 = __ldg(&g_scol[jn + 3]);
        }

        float2 k0 = *(const float2*)(g_K + (size_t)u0 * DD + lane * 2);
        float2 k1 = *(const float2*)(g_K + (size_t)u1 * DD + lane * 2);
        float2 k2 = *(const float2*)(g_K + (size_t)u2 * DD + lane * 2);
        float2 k3 = *(const float2*)(g_K + (size_t)u3 * DD + lane * 2);
        float2 v0 = *(const float2*)(g_V + (size_t)u0 * DD + lane * 2);
        float2 v1 = *(const float2*)(g_V + (size_t)u1 * DD + lane * 2);
        float2 v2 = *(const float2*)(g_V + (size_t)u2 * DD + lane * 2);
        float2 v3 = *(const float2*)(g_V + (size_t)u3 * DD + lane * 2);

        float p0 = q.x * k0.x + q.y * k0.y;
        float p1 = q.x * k1.x + q.y * k1.y;
        float p2 = q.x * k2.x + q.y * k2.y;
        float p3 = q.x * k3.x + q.y * k3.y;

        p0 += __shfl_xor_sync(0xffffffffu, p0, 1);
        p1 += __shfl_xor_sync(0xffffffffu, p1, 1);
        p2 += __shfl_xor_sync(0xffffffffu, p2, 1);
        p3 += __shfl_xor_sync(0xffffffffu, p3, 1);
        p0 += __shfl_xor_sync(0xffffffffu, p0, 2);
        p1 += __shfl_xor_sync(0xffffffffu, p1, 2);
        p2 += __shfl_xor_sync(0xffffffffu, p2, 2);
        p3 += __shfl_xor_sync(0xffffffffu, p3, 2);
        p0 += __shfl_xor_sync(0xffffffffu, p0, 4);
        p1 += __shfl_xor_sync(0xffffffffu, p1, 4);
        p2 += __shfl_xor_sync(0xffffffffu, p2, 4);
        p3 += __shfl_xor_sync(0xffffffffu, p3, 4);

        float e0 = __expf(fminf(10.f, fmaxf(-10.f, p0)));
        float e1 = __expf(fminf(10.f, fmaxf(-10.f, p1)));
        float e2 = __expf(fminf(10.f, fmaxf(-10.f, p2)));
        float e3 = __expf(fminf(10.f, fmaxf(-10.f, p3)));

        na += (e0 + e1) + (e2 + e3);
        acc.x += e0 * v0.x + e1 * v1.x + e2 * v2.x + e3 * v3.x;
        acc.y += e0 * v0.y + e1 * v1.y + e2 * v2.y + e3 * v3.y;

        j = jn;
    }

    for (; j < end; j++) {
        int c = __ldg(&g_scol[j]);
        float2 kv = *(const float2*)(g_K + (size_t)c * DD + lane * 2);
        float2 vv = *(const float2*)(g_V + (size_t)c * DD + lane * 2);
        float p = q.x * kv.x + q.y * kv.y;
        p += __shfl_xor_sync(0xffffffffu, p, 1);
        p += __shfl_xor_sync(0xffffffffu, p, 2);
        p += __shfl_xor_sync(0xffffffffu, p, 4);
        float ea = __expf(fminf(10.f, fmaxf(-10.f, p)));
        na += ea;
        acc.x += ea * vv.x;
        acc.y += ea * vv.y;
    }

    float inv = 1.f / (na + 1e-8f);
    *(float2*)(out + (size_t)warp * DD + lane * 2) =
        make_float2(acc.x * inv, acc.y * inv);
}

// ---------------------------------------------------------------------------
extern "C" void kernel_launch(void* const* d_in, const int* in_sizes, int n_in,
                              void* d_out, int out_size)
{
    const float* X  = (const float*)d_in[0];
    const float* Wq = (const float*)d_in[1];
    const float* Wk = (const float*)d_in[2];
    const float* Wv = (const float*)d_in[3];
    const int*   ei = (const int*)d_in[4];
    const int* rows = ei;
    const int* cols = ei + EE;
    float* out = (float*)d_out;

    (void)in_sizes; (void)n_in; (void)out_size;

    // zero counts in 3 parts (launches 1-3; proj stays at ncu capture slot #4)
    int third = (NN + 2) / 3;
    zero_cnt_part<<<(third + 255) / 256, 256>>>(0, third);
    zero_cnt_part<<<(third + 255) / 256, 256>>>(third, third);
    zero_cnt_part<<<(third + 255) / 256, 256>>>(2 * third, NN - 2 * third);

    // 1) node projections (tiled GEMM, grid.y = matrix; launch #4 — profiled)
    dim3 pgrid((NN + PB_NODES - 1) / PB_NODES, 3);
    proj_kernel<<<pgrid, 256>>>(X, Wq, Wk, Wv);

    // 2) CSR build by destination row
    hist_kernel<<<(EE / 4 + 255) / 256, 256>>>(rows);
    int nb = (NN + 1023) / 1024;
    scan_block_kernel<<<nb, 1024>>>();
    scan_sums_kernel<<<1, 32>>>(nb);
    add_off_kernel<<<(NN + 255) / 256, 256>>>();
    scatter_kernel<<<(EE / 4 + 255) / 256, 256>>>(rows, cols);

    // 3) fused gather + softmax + aggregate (one warp per node)
    aggregate_kernel<<<(NN * 32 + 255) / 256, 256>>>(out);
}